// round 16
// baseline (speedup 1.0000x reference)
#include <cuda_runtime.h>
#include <cuda_fp16.h>
#include <cstdint>
#include <cstddef>

// Problem constants (fixed by the reference setup_inputs).
#define N_NODES 100000
#define N_EDGES 1600000
#define IN_DIM  512
#define OUT_DIM 256

// ---------------------------------------------------------------------------
// Device-global scratch (allocation-free contract).
// ---------------------------------------------------------------------------
__device__ int    d_count[N_NODES];
__device__ int    d_row_ptr[N_NODES + 1];
__device__ int    d_woff[N_NODES];
__device__ int    d_bsums[128];
__device__ int2   d_perm[N_EDGES];                               // {col, val bits}
__device__ __half d_support_h[(size_t)N_NODES * OUT_DIM];        // x @ W (fp16, 51MB)
__device__ __half d_wt_h[OUT_DIM * IN_DIM];                      // W^T (fp16)

#define SCAN_BLK 1024
#define N_SCAN_BLOCKS ((N_NODES + SCAN_BLK - 1) / SCAN_BLK)   // 98

#define SW128(o) ((o) ^ (((o) >> 3) & 0x70))

__device__ __forceinline__ uint32_t smem_u32(const void* p) {
    uint32_t a;
    asm("{ .reg .u64 t; cvta.to.shared.u64 t, %1; cvt.u32.u64 %0, t; }"
        : "=r"(a) : "l"(p));
    return a;
}
__device__ __forceinline__ void ldsm_x4(uint32_t& r0, uint32_t& r1,
                                        uint32_t& r2, uint32_t& r3,
                                        uint32_t addr) {
    asm volatile("ldmatrix.sync.aligned.m8n8.x4.shared.b16 {%0,%1,%2,%3}, [%4];"
                 : "=r"(r0), "=r"(r1), "=r"(r2), "=r"(r3) : "r"(addr));
}
__device__ __forceinline__ void mma16816h(float* c, const uint32_t* a,
                                          const uint32_t* b) {
    asm volatile(
        "mma.sync.aligned.m16n8k16.row.col.f32.f16.f16.f32 "
        "{%0,%1,%2,%3}, {%4,%5,%6,%7}, {%8,%9}, {%0,%1,%2,%3};"
        : "+f"(c[0]), "+f"(c[1]), "+f"(c[2]), "+f"(c[3])
        : "r"(a[0]), "r"(a[1]), "r"(a[2]), "r"(a[3]), "r"(b[0]), "r"(b[1]));
}
__device__ __forceinline__ void cp_async16(uint32_t dst, const void* src) {
    asm volatile("cp.async.cg.shared.global [%0], [%1], 16;"
                 :: "r"(dst), "l"(src) : "memory");
}
#define CP_COMMIT() asm volatile("cp.async.commit_group;" ::: "memory")
#define CP_WAIT0()  asm volatile("cp.async.wait_group 0;" ::: "memory")

// ---------------------------------------------------------------------------
// CSR construction
// ---------------------------------------------------------------------------
__global__ void zero_counts_kernel() {
    int i = blockIdx.x * blockDim.x + threadIdx.x;
    if (i < N_NODES) d_count[i] = 0;
}
__global__ void scan_partial_kernel() {
    __shared__ int warp_sums[32];
    int i = blockIdx.x * SCAN_BLK + threadIdx.x;
    int lane = threadIdx.x & 31, w = threadIdx.x >> 5;
    int orig = (i < N_NODES) ? d_count[i] : 0;
    int v = orig;
    #pragma unroll
    for (int o = 1; o < 32; o <<= 1) {
        int n = __shfl_up_sync(0xffffffffu, v, o);
        if (lane >= o) v += n;
    }
    if (lane == 31) warp_sums[w] = v;
    __syncthreads();
    if (w == 0) {
        int s = warp_sums[lane];
        #pragma unroll
        for (int o = 1; o < 32; o <<= 1) {
            int n = __shfl_up_sync(0xffffffffu, s, o);
            if (lane >= o) s += n;
        }
        warp_sums[lane] = s;
    }
    __syncthreads();
    int prefix = (w > 0) ? warp_sums[w - 1] : 0;
    int inc = v + prefix;
    if (i < N_NODES) d_row_ptr[i] = inc - orig;
    if (threadIdx.x == SCAN_BLK - 1) d_bsums[blockIdx.x] = inc;
}
__global__ void scan_add_kernel() {
    __shared__ int pref_s;
    int lane = threadIdx.x & 31;
    if (threadIdx.x < 32) {
        int acc = 0;
        for (int b = lane; b < blockIdx.x; b += 32) acc += d_bsums[b];
        #pragma unroll
        for (int o = 16; o > 0; o >>= 1)
            acc += __shfl_down_sync(0xffffffffu, acc, o);
        if (lane == 0) pref_s = acc;
    }
    __syncthreads();
    int pref = pref_s;
    int i = blockIdx.x * SCAN_BLK + threadIdx.x;
    if (i < N_NODES) {
        int rp = d_row_ptr[i] + pref;
        d_row_ptr[i] = rp;
        d_woff[i] = rp;
    }
    if (blockIdx.x == 0 && threadIdx.x == 0) d_row_ptr[N_NODES] = N_EDGES;
}
// Scatter: 8 edges per thread (two int4 groups) for atomic MLP.
__global__ void scatter_kernel(const int4* __restrict__ erow4,
                               const int4* __restrict__ ecol4,
                               const float4* __restrict__ eval4) {
    int e = blockIdx.x * blockDim.x + threadIdx.x;   // over N_EDGES/8
    if (e < N_EDGES / 8) {
        int4   r0 = erow4[e * 2],     r1 = erow4[e * 2 + 1];
        int4   c0 = ecol4[e * 2],     c1 = ecol4[e * 2 + 1];
        float4 v0 = eval4[e * 2],     v1 = eval4[e * 2 + 1];
        int p0 = atomicAdd(&d_woff[r0.x], 1);
        int p1 = atomicAdd(&d_woff[r0.y], 1);
        int p2 = atomicAdd(&d_woff[r0.z], 1);
        int p3 = atomicAdd(&d_woff[r0.w], 1);
        int p4 = atomicAdd(&d_woff[r1.x], 1);
        int p5 = atomicAdd(&d_woff[r1.y], 1);
        int p6 = atomicAdd(&d_woff[r1.z], 1);
        int p7 = atomicAdd(&d_woff[r1.w], 1);
        d_perm[p0] = make_int2(c0.x, __float_as_int(v0.x));
        d_perm[p1] = make_int2(c0.y, __float_as_int(v0.y));
        d_perm[p2] = make_int2(c0.z, __float_as_int(v0.z));
        d_perm[p3] = make_int2(c0.w, __float_as_int(v0.w));
        d_perm[p4] = make_int2(c1.x, __float_as_int(v1.x));
        d_perm[p5] = make_int2(c1.y, __float_as_int(v1.y));
        d_perm[p6] = make_int2(c1.z, __float_as_int(v1.z));
        d_perm[p7] = make_int2(c1.w, __float_as_int(v1.w));
    }
}

// ---------------------------------------------------------------------------
// W preprocessing: transpose W [512,256] fp32 -> W^T [256,512] fp16
// ---------------------------------------------------------------------------
__global__ void convW_kernel(const float* __restrict__ W) {
    int idx = blockIdx.x * blockDim.x + threadIdx.x;
    if (idx < IN_DIM * OUT_DIM) {
        int k = idx / OUT_DIM, n = idx % OUT_DIM;
        d_wt_h[n * IN_DIM + k] = __float2half(W[idx]);
    }
}

// ---------------------------------------------------------------------------
// Fused HMMA GEMM + edge histogram.
//   Blocks [0, GEMM_TILES_M): 128x256 single-pass GEMM (validated R14).
//   Blocks [GEMM_TILES_M, +HIST_BLOCKS): grid-strided int4 histogram.
//   Hist is independent of GEMM dataflow; zero_counts runs before this
//   kernel, scan after it -> no races. Same-launch blocks co-schedule,
//   so hist hides in the GEMM tail instead of serializing.
// ---------------------------------------------------------------------------
#define BMM 128
#define BNN 256
#define KC  64
#define N_CHUNK (IN_DIM / KC)                       // 8
#define GEMM_TILES_M ((N_NODES + BMM - 1) / BMM)    // 782
#define HIST_BLOCKS 98
#define GEMM_THREADS 512
#define SM_A_OFF  0
#define SM_B0_OFF (BMM * 128)                       // 16384
#define SM_B1_OFF (SM_B0_OFF + BNN * 128)           // 49152
#define GEMM_SMEM (SM_B1_OFF + BNN * 128)           // 81920

__global__ __launch_bounds__(GEMM_THREADS, 1)
void gemm_hist_kernel(const float* __restrict__ X,
                      const int4* __restrict__ erow4) {
    // ---- Histogram role ----
    if (blockIdx.x >= GEMM_TILES_M) {
        int base = (blockIdx.x - GEMM_TILES_M) * GEMM_THREADS + threadIdx.x;
        const int stride = HIST_BLOCKS * GEMM_THREADS;
        for (int e = base; e < N_EDGES / 4; e += stride) {
            int4 r = erow4[e];
            atomicAdd(&d_count[r.x], 1);
            atomicAdd(&d_count[r.y], 1);
            atomicAdd(&d_count[r.z], 1);
            atomicAdd(&d_count[r.w], 1);
        }
        return;
    }

    // ---- GEMM role (R14 structure, validated) ----
    extern __shared__ char smem[];
    char* sA  = smem + SM_A_OFF;
    char* sB0 = smem + SM_B0_OFF;
    char* sB1 = smem + SM_B1_OFF;

    const int tid  = threadIdx.x;
    const int lane = tid & 31;
    const int wid  = tid >> 5;          // 0..15
    const int wm   = wid >> 2;          // 0..3
    const int wn   = wid & 3;           // 0..3
    const int gr   = blockIdx.x * BMM;

    const uint32_t sa  = smem_u32(sA);
    const uint32_t sb0 = smem_u32(sB0);
    const uint32_t sb1 = smem_u32(sB1);

    float acc[2][8][4];
    #pragma unroll
    for (int i = 0; i < 2; i++)
        #pragma unroll
        for (int j = 0; j < 8; j++)
            #pragma unroll
            for (int q = 0; q < 4; q++) acc[i][j][q] = 0.f;

    const int aq   = tid & 15;          // float4 index along k (0..15)
    const int arow = tid >> 4;          // 0..31; rows t*32 + arow

    const int a_row = lane & 15;
    const int a_kb  = (lane & 16) ? 16 : 0;
    const int b_n   = (lane & 7) + ((lane & 16) ? 8 : 0);
    const int b_kb  = (lane & 8) ? 16 : 0;

    float4 av[4];

    auto load_A_regs = [&](int k0) {
        #pragma unroll
        for (int t = 0; t < 4; t++) {
            int grow = gr + t * 32 + arow;
            av[t] = make_float4(0.f, 0.f, 0.f, 0.f);
            if (grow < N_NODES)
                av[t] = *(const float4*)(X + (size_t)grow * IN_DIM + k0 + aq * 4);
        }
    };
    auto store_A_regs = [&]() {
        #pragma unroll
        for (int t = 0; t < 4; t++) {
            int row = t * 32 + arow;
            float4 v = av[t];
            __half2 p0 = __floats2half2_rn(v.x, v.y);
            __half2 p1 = __floats2half2_rn(v.z, v.w);
            uint2 hp;
            hp.x = *(uint32_t*)&p0;
            hp.y = *(uint32_t*)&p1;
            *(uint2*)(sA + SW128((uint32_t)(row * 128 + aq * 8))) = hp;
        }
    };
    auto issue_B = [&](int k0, int buf) {
        char* base = buf ? sB1 : sB0;
        #pragma unroll
        for (int t = 0; t < 4; t++) {
            int idx = t * GEMM_THREADS + tid;
            int n = idx >> 3;            // 0..255
            int u = idx & 7;
            cp_async16(smem_u32(base + SW128((uint32_t)(n * 128 + u * 16))),
                       d_wt_h + (size_t)n * IN_DIM + k0 + u * 8);
        }
        CP_COMMIT();
    };

    issue_B(0, 0);
    load_A_regs(0);
    CP_WAIT0();
    store_A_regs();
    __syncthreads();

    for (int c = 0; c < N_CHUNK; c++) {
        if (c + 1 < N_CHUNK) {
            issue_B((c + 1) * KC, (c + 1) & 1);
            load_A_regs((c + 1) * KC);
        }
        const uint32_t sb = (c & 1) ? sb1 : sb0;

        #pragma unroll
        for (int ks = 0; ks < 4; ks++) {
            uint32_t ah[2][4], bf[8][2];
            #pragma unroll
            for (int i = 0; i < 2; i++) {
                uint32_t off = (uint32_t)((wm * 32 + i * 16 + a_row) * 128 + ks * 32 + a_kb);
                ldsm_x4(ah[i][0], ah[i][1], ah[i][2], ah[i][3], sa + SW128(off));
            }
            #pragma unroll
            for (int j = 0; j < 8; j += 2) {
                uint32_t off = (uint32_t)((wn * 64 + j * 8 + b_n) * 128 + ks * 32 + b_kb);
                ldsm_x4(bf[j][0], bf[j][1], bf[j + 1][0], bf[j + 1][1], sb + SW128(off));
            }
            #pragma unroll
            for (int i = 0; i < 2; i++)
                #pragma unroll
                for (int j = 0; j < 8; j++)
                    mma16816h(acc[i][j], ah[i], bf[j]);
        }

        if (c + 1 < N_CHUNK) {
            CP_WAIT0();
            __syncthreads();
            store_A_regs();
            __syncthreads();
        }
    }

    const int col = wn * 64 + (lane & 3) * 2;
    #pragma unroll
    for (int i = 0; i < 2; i++) {
        int row0 = gr + wm * 32 + i * 16 + (lane >> 2);
        #pragma unroll
        for (int j = 0; j < 8; j++) {
            if (row0 < N_NODES)
                *(__half2*)(d_support_h + (size_t)row0 * OUT_DIM + col + j * 8) =
                    __floats2half2_rn(acc[i][j][0], acc[i][j][1]);
            if (row0 + 8 < N_NODES)
                *(__half2*)(d_support_h + (size_t)(row0 + 8) * OUT_DIM + col + j * 8) =
                    __floats2half2_rn(acc[i][j][2], acc[i][j][3]);
        }
    }
}

// ---------------------------------------------------------------------------
// SpMM: warp per row; fp16 support gathers; 8-edge unroll (validated R13/R14).
// ---------------------------------------------------------------------------
__global__ __launch_bounds__(256)
void spmm_kernel(const float* __restrict__ bias, float* __restrict__ out) {
    int warp = (blockIdx.x * blockDim.x + threadIdx.x) >> 5;
    int lane = threadIdx.x & 31;
    if (warp >= N_NODES) return;

    int s = d_row_ptr[warp];
    int e = d_row_ptr[warp + 1];

    const uint4* S = (const uint4*)d_support_h;   // 32 uint4 per row
    float acc[8];
    #pragma unroll
    for (int q = 0; q < 8; q++) acc[q] = 0.f;

    int i = s;
    for (; i + 7 < e; i += 8) {
        int2 ed[8];
        #pragma unroll
        for (int t = 0; t < 8; t++) ed[t] = __ldcs(&d_perm[i + t]);
        uint4 u[8];
        #pragma unroll
        for (int t = 0; t < 8; t++) u[t] = S[(size_t)ed[t].x * 32 + lane];
        #pragma unroll
        for (int t = 0; t < 8; t++) {
            float v = __int_as_float(ed[t].y);
            const __half2* h = (const __half2*)&u[t];
            #pragma unroll
            for (int q = 0; q < 4; q++) {
                float2 f = __half22float2(h[q]);
                acc[q * 2]     += v * f.x;
                acc[q * 2 + 1] += v * f.y;
            }
        }
    }
    for (; i + 3 < e; i += 4) {
        int2 ed[4];
        #pragma unroll
        for (int t = 0; t < 4; t++) ed[t] = __ldcs(&d_perm[i + t]);
        uint4 u[4];
        #pragma unroll
        for (int t = 0; t < 4; t++) u[t] = S[(size_t)ed[t].x * 32 + lane];
        #pragma unroll
        for (int t = 0; t < 4; t++) {
            float v = __int_as_float(ed[t].y);
            const __half2* h = (const __half2*)&u[t];
            #pragma unroll
            for (int q = 0; q < 4; q++) {
                float2 f = __half22float2(h[q]);
                acc[q * 2]     += v * f.x;
                acc[q * 2 + 1] += v * f.y;
            }
        }
    }
    for (; i < e; i++) {
        int2 e0 = __ldcs(&d_perm[i]);
        float v0 = __int_as_float(e0.y);
        uint4 u0 = S[(size_t)e0.x * 32 + lane];
        const __half2* h0 = (const __half2*)&u0;
        #pragma unroll
        for (int q = 0; q < 4; q++) {
            float2 f0 = __half22float2(h0[q]);
            acc[q * 2]     += v0 * f0.x;
            acc[q * 2 + 1] += v0 * f0.y;
        }
    }

    const float4* b4 = (const float4*)bias;
    float4 b0 = b4[lane * 2], b1 = b4[lane * 2 + 1];
    float4 r0, r1;
    r0.x = fmaxf(acc[0] + b0.x, 0.f); r0.y = fmaxf(acc[1] + b0.y, 0.f);
    r0.z = fmaxf(acc[2] + b0.z, 0.f); r0.w = fmaxf(acc[3] + b0.w, 0.f);
    r1.x = fmaxf(acc[4] + b1.x, 0.f); r1.y = fmaxf(acc[5] + b1.y, 0.f);
    r1.z = fmaxf(acc[6] + b1.z, 0.f); r1.w = fmaxf(acc[7] + b1.w, 0.f);

    float4* o = (float4*)out + (size_t)warp * (OUT_DIM / 4) + lane * 2;
    __stcs(o,     r0);
    __stcs(o + 1, r1);
}

// ---------------------------------------------------------------------------
// Launch: single stream. Hist is fused into the GEMM launch; zero before,
// scan/scatter after, SpMM last.
// ---------------------------------------------------------------------------
extern "C" void kernel_launch(void* const* d_in, const int* in_sizes, int n_in,
                              void* d_out, int out_size) {
    const float* x    = (const float*)d_in[0];   // [100000, 512]
    const float* W    = (const float*)d_in[1];   // [512, 256]
    const float* b    = (const float*)d_in[2];   // [256]
    const int*   erow = (const int*)d_in[3];     // [1600000]
    const int*   ecol = (const int*)d_in[4];     // [1600000]
    const float* eval = (const float*)d_in[5];   // [1600000]
    float* out = (float*)d_out;                  // [100000, 256]

    (void)in_sizes; (void)n_in; (void)out_size;

    // Unconditional (capture-safe, deterministic).
    cudaFuncSetAttribute(gemm_hist_kernel,
                         cudaFuncAttributeMaxDynamicSharedMemorySize, GEMM_SMEM);

    // Prolog: zero counts + W convert (tiny).
    zero_counts_kernel<<<(N_NODES + 255) / 256, 256>>>();
    convW_kernel<<<(IN_DIM * OUT_DIM + 255) / 256, 256>>>(W);

    // Fused GEMM (single x pass) + histogram (tail-filled).
    gemm_hist_kernel<<<GEMM_TILES_M + HIST_BLOCKS, GEMM_THREADS, GEMM_SMEM>>>(
        x, (const int4*)erow);

    // Scan + scatter.
    scan_partial_kernel<<<N_SCAN_BLOCKS, SCAN_BLK>>>();
    scan_add_kernel<<<N_SCAN_BLOCKS, SCAN_BLK>>>();
    scatter_kernel<<<(N_EDGES / 8 + 255) / 256, 256>>>(
        (const int4*)erow, (const int4*)ecol, (const float4*)eval);

    // SpMM + bias + ReLU.
    spmm_kernel<<<(N_NODES * 32 + 255) / 256, 256>>>(b, out);
}

// round 17
// speedup vs baseline: 1.0103x; 1.0103x over previous
#include <cuda_runtime.h>
#include <cuda_fp16.h>
#include <cstdint>
#include <cstddef>

// Problem constants (fixed by the reference setup_inputs).
#define N_NODES 100000
#define N_EDGES 1600000
#define IN_DIM  512
#define OUT_DIM 256

// ---------------------------------------------------------------------------
// Device-global scratch (allocation-free contract).
// ---------------------------------------------------------------------------
__device__ int    d_count[N_NODES];
__device__ int    d_row_ptr[N_NODES + 1];
__device__ int    d_woff[N_NODES];
__device__ int    d_bsums[128];
__device__ int2   d_perm[N_EDGES];                               // {col, val bits}
__device__ __half d_support_h[(size_t)N_NODES * OUT_DIM];        // x @ W (fp16, 51MB)
__device__ __half d_wt_h[OUT_DIM * IN_DIM];                      // W^T (fp16)

#define SCAN_BLK 1024
#define N_SCAN_BLOCKS ((N_NODES + SCAN_BLK - 1) / SCAN_BLK)   // 98

#define SW128(o) ((o) ^ (((o) >> 3) & 0x70))

__device__ __forceinline__ uint32_t smem_u32(const void* p) {
    uint32_t a;
    asm("{ .reg .u64 t; cvta.to.shared.u64 t, %1; cvt.u32.u64 %0, t; }"
        : "=r"(a) : "l"(p));
    return a;
}
__device__ __forceinline__ void ldsm_x4(uint32_t& r0, uint32_t& r1,
                                        uint32_t& r2, uint32_t& r3,
                                        uint32_t addr) {
    asm volatile("ldmatrix.sync.aligned.m8n8.x4.shared.b16 {%0,%1,%2,%3}, [%4];"
                 : "=r"(r0), "=r"(r1), "=r"(r2), "=r"(r3) : "r"(addr));
}
__device__ __forceinline__ void mma16816h(float* c, const uint32_t* a,
                                          const uint32_t* b) {
    asm volatile(
        "mma.sync.aligned.m16n8k16.row.col.f32.f16.f16.f32 "
        "{%0,%1,%2,%3}, {%4,%5,%6,%7}, {%8,%9}, {%0,%1,%2,%3};"
        : "+f"(c[0]), "+f"(c[1]), "+f"(c[2]), "+f"(c[3])
        : "r"(a[0]), "r"(a[1]), "r"(a[2]), "r"(a[3]), "r"(b[0]), "r"(b[1]));
}
__device__ __forceinline__ void cp_async16(uint32_t dst, const void* src) {
    asm volatile("cp.async.cg.shared.global [%0], [%1], 16;"
                 :: "r"(dst), "l"(src) : "memory");
}
#define CP_COMMIT() asm volatile("cp.async.commit_group;" ::: "memory")
#define CP_WAIT0()  asm volatile("cp.async.wait_group 0;" ::: "memory")

// ---------------------------------------------------------------------------
// CSR construction (R14-validated, except scatter now 8 edges/thread)
// ---------------------------------------------------------------------------
__global__ void zero_counts_kernel() {
    int i = blockIdx.x * blockDim.x + threadIdx.x;
    if (i < N_NODES) d_count[i] = 0;
}
__global__ void hist_kernel(const int4* __restrict__ erow4) {
    int e = blockIdx.x * blockDim.x + threadIdx.x;
    if (e < N_EDGES / 4) {
        int4 r = erow4[e];
        atomicAdd(&d_count[r.x], 1);
        atomicAdd(&d_count[r.y], 1);
        atomicAdd(&d_count[r.z], 1);
        atomicAdd(&d_count[r.w], 1);
    }
}
__global__ void scan_partial_kernel() {
    __shared__ int warp_sums[32];
    int i = blockIdx.x * SCAN_BLK + threadIdx.x;
    int lane = threadIdx.x & 31, w = threadIdx.x >> 5;
    int orig = (i < N_NODES) ? d_count[i] : 0;
    int v = orig;
    #pragma unroll
    for (int o = 1; o < 32; o <<= 1) {
        int n = __shfl_up_sync(0xffffffffu, v, o);
        if (lane >= o) v += n;
    }
    if (lane == 31) warp_sums[w] = v;
    __syncthreads();
    if (w == 0) {
        int s = warp_sums[lane];
        #pragma unroll
        for (int o = 1; o < 32; o <<= 1) {
            int n = __shfl_up_sync(0xffffffffu, s, o);
            if (lane >= o) s += n;
        }
        warp_sums[lane] = s;
    }
    __syncthreads();
    int prefix = (w > 0) ? warp_sums[w - 1] : 0;
    int inc = v + prefix;
    if (i < N_NODES) d_row_ptr[i] = inc - orig;
    if (threadIdx.x == SCAN_BLK - 1) d_bsums[blockIdx.x] = inc;
}
__global__ void scan_add_kernel() {
    __shared__ int pref_s;
    int lane = threadIdx.x & 31;
    if (threadIdx.x < 32) {
        int acc = 0;
        for (int b = lane; b < blockIdx.x; b += 32) acc += d_bsums[b];
        #pragma unroll
        for (int o = 16; o > 0; o >>= 1)
            acc += __shfl_down_sync(0xffffffffu, acc, o);
        if (lane == 0) pref_s = acc;
    }
    __syncthreads();
    int pref = pref_s;
    int i = blockIdx.x * SCAN_BLK + threadIdx.x;
    if (i < N_NODES) {
        int rp = d_row_ptr[i] + pref;
        d_row_ptr[i] = rp;
        d_woff[i] = rp;
    }
    if (blockIdx.x == 0 && threadIdx.x == 0) d_row_ptr[N_NODES] = N_EDGES;
}
// Scatter: 8 edges per thread (two int4 groups) for atomic MLP.
__global__ void scatter_kernel(const int4* __restrict__ erow4,
                               const int4* __restrict__ ecol4,
                               const float4* __restrict__ eval4) {
    int e = blockIdx.x * blockDim.x + threadIdx.x;   // over N_EDGES/8
    if (e < N_EDGES / 8) {
        int4   r0 = erow4[e * 2],     r1 = erow4[e * 2 + 1];
        int4   c0 = ecol4[e * 2],     c1 = ecol4[e * 2 + 1];
        float4 v0 = eval4[e * 2],     v1 = eval4[e * 2 + 1];
        int p0 = atomicAdd(&d_woff[r0.x], 1);
        int p1 = atomicAdd(&d_woff[r0.y], 1);
        int p2 = atomicAdd(&d_woff[r0.z], 1);
        int p3 = atomicAdd(&d_woff[r0.w], 1);
        int p4 = atomicAdd(&d_woff[r1.x], 1);
        int p5 = atomicAdd(&d_woff[r1.y], 1);
        int p6 = atomicAdd(&d_woff[r1.z], 1);
        int p7 = atomicAdd(&d_woff[r1.w], 1);
        d_perm[p0] = make_int2(c0.x, __float_as_int(v0.x));
        d_perm[p1] = make_int2(c0.y, __float_as_int(v0.y));
        d_perm[p2] = make_int2(c0.z, __float_as_int(v0.z));
        d_perm[p3] = make_int2(c0.w, __float_as_int(v0.w));
        d_perm[p4] = make_int2(c1.x, __float_as_int(v1.x));
        d_perm[p5] = make_int2(c1.y, __float_as_int(v1.y));
        d_perm[p6] = make_int2(c1.z, __float_as_int(v1.z));
        d_perm[p7] = make_int2(c1.w, __float_as_int(v1.w));
    }
}

// ---------------------------------------------------------------------------
// W preprocessing: transpose W [512,256] fp32 -> W^T [256,512] fp16
// ---------------------------------------------------------------------------
__global__ void convW_kernel(const float* __restrict__ W) {
    int idx = blockIdx.x * blockDim.x + threadIdx.x;
    if (idx < IN_DIM * OUT_DIM) {
        int k = idx / OUT_DIM, n = idx % OUT_DIM;
        d_wt_h[n * IN_DIM + k] = __float2half(W[idx]);
    }
}

// ---------------------------------------------------------------------------
// HMMA GEMM (R14-validated, 215.2us config): single-product fp16 mma,
// block 128x256 (x read exactly once), 512 threads, 16 warps 4Mx4N,
// KC=64 pipelined, dynamic smem 80KB.
// ---------------------------------------------------------------------------
#define BMM 128
#define BNN 256
#define KC  64
#define N_CHUNK (IN_DIM / KC)                       // 8
#define GEMM_TILES_M ((N_NODES + BMM - 1) / BMM)    // 782
#define GEMM_THREADS 512
#define SM_A_OFF  0
#define SM_B0_OFF (BMM * 128)                       // 16384
#define SM_B1_OFF (SM_B0_OFF + BNN * 128)           // 49152
#define GEMM_SMEM (SM_B1_OFF + BNN * 128)           // 81920

__global__ __launch_bounds__(GEMM_THREADS, 1)
void gemm_hmma_kernel(const float* __restrict__ X) {
    extern __shared__ char smem[];
    char* sA  = smem + SM_A_OFF;
    char* sB0 = smem + SM_B0_OFF;
    char* sB1 = smem + SM_B1_OFF;

    const int tid  = threadIdx.x;
    const int lane = tid & 31;
    const int wid  = tid >> 5;          // 0..15
    const int wm   = wid >> 2;          // 0..3
    const int wn   = wid & 3;           // 0..3
    const int gr   = blockIdx.x * BMM;

    const uint32_t sa  = smem_u32(sA);
    const uint32_t sb0 = smem_u32(sB0);
    const uint32_t sb1 = smem_u32(sB1);

    float acc[2][8][4];
    #pragma unroll
    for (int i = 0; i < 2; i++)
        #pragma unroll
        for (int j = 0; j < 8; j++)
            #pragma unroll
            for (int q = 0; q < 4; q++) acc[i][j][q] = 0.f;

    const int aq   = tid & 15;          // float4 index along k (0..15)
    const int arow = tid >> 4;          // 0..31; rows t*32 + arow

    const int a_row = lane & 15;
    const int a_kb  = (lane & 16) ? 16 : 0;
    const int b_n   = (lane & 7) + ((lane & 16) ? 8 : 0);
    const int b_kb  = (lane & 8) ? 16 : 0;

    float4 av[4];

    auto load_A_regs = [&](int k0) {
        #pragma unroll
        for (int t = 0; t < 4; t++) {
            int grow = gr + t * 32 + arow;
            av[t] = make_float4(0.f, 0.f, 0.f, 0.f);
            if (grow < N_NODES)
                av[t] = *(const float4*)(X + (size_t)grow * IN_DIM + k0 + aq * 4);
        }
    };
    auto store_A_regs = [&]() {
        #pragma unroll
        for (int t = 0; t < 4; t++) {
            int row = t * 32 + arow;
            float4 v = av[t];
            __half2 p0 = __floats2half2_rn(v.x, v.y);
            __half2 p1 = __floats2half2_rn(v.z, v.w);
            uint2 hp;
            hp.x = *(uint32_t*)&p0;
            hp.y = *(uint32_t*)&p1;
            *(uint2*)(sA + SW128((uint32_t)(row * 128 + aq * 8))) = hp;
        }
    };
    auto issue_B = [&](int k0, int buf) {
        char* base = buf ? sB1 : sB0;
        #pragma unroll
        for (int t = 0; t < 4; t++) {
            int idx = t * GEMM_THREADS + tid;
            int n = idx >> 3;            // 0..255
            int u = idx & 7;
            cp_async16(smem_u32(base + SW128((uint32_t)(n * 128 + u * 16))),
                       d_wt_h + (size_t)n * IN_DIM + k0 + u * 8);
        }
        CP_COMMIT();
    };

    issue_B(0, 0);
    load_A_regs(0);
    CP_WAIT0();
    store_A_regs();
    __syncthreads();

    for (int c = 0; c < N_CHUNK; c++) {
        if (c + 1 < N_CHUNK) {
            issue_B((c + 1) * KC, (c + 1) & 1);
            load_A_regs((c + 1) * KC);
        }
        const uint32_t sb = (c & 1) ? sb1 : sb0;

        #pragma unroll
        for (int ks = 0; ks < 4; ks++) {
            uint32_t ah[2][4], bf[8][2];
            #pragma unroll
            for (int i = 0; i < 2; i++) {
                uint32_t off = (uint32_t)((wm * 32 + i * 16 + a_row) * 128 + ks * 32 + a_kb);
                ldsm_x4(ah[i][0], ah[i][1], ah[i][2], ah[i][3], sa + SW128(off));
            }
            #pragma unroll
            for (int j = 0; j < 8; j += 2) {
                uint32_t off = (uint32_t)((wn * 64 + j * 8 + b_n) * 128 + ks * 32 + b_kb);
                ldsm_x4(bf[j][0], bf[j][1], bf[j + 1][0], bf[j + 1][1], sb + SW128(off));
            }
            #pragma unroll
            for (int i = 0; i < 2; i++)
                #pragma unroll
                for (int j = 0; j < 8; j++)
                    mma16816h(acc[i][j], ah[i], bf[j]);
        }

        if (c + 1 < N_CHUNK) {
            CP_WAIT0();
            __syncthreads();
            store_A_regs();
            __syncthreads();
        }
    }

    const int col = wn * 64 + (lane & 3) * 2;
    #pragma unroll
    for (int i = 0; i < 2; i++) {
        int row0 = gr + wm * 32 + i * 16 + (lane >> 2);
        #pragma unroll
        for (int j = 0; j < 8; j++) {
            if (row0 < N_NODES)
                *(__half2*)(d_support_h + (size_t)row0 * OUT_DIM + col + j * 8) =
                    __floats2half2_rn(acc[i][j][0], acc[i][j][1]);
            if (row0 + 8 < N_NODES)
                *(__half2*)(d_support_h + (size_t)(row0 + 8) * OUT_DIM + col + j * 8) =
                    __floats2half2_rn(acc[i][j][2], acc[i][j][3]);
        }
    }
}

// ---------------------------------------------------------------------------
// SpMM: warp per row; fp16 support gathers; 8-edge unroll (validated R13/R14).
// ---------------------------------------------------------------------------
__global__ __launch_bounds__(256)
void spmm_kernel(const float* __restrict__ bias, float* __restrict__ out) {
    int warp = (blockIdx.x * blockDim.x + threadIdx.x) >> 5;
    int lane = threadIdx.x & 31;
    if (warp >= N_NODES) return;

    int s = d_row_ptr[warp];
    int e = d_row_ptr[warp + 1];

    const uint4* S = (const uint4*)d_support_h;   // 32 uint4 per row
    float acc[8];
    #pragma unroll
    for (int q = 0; q < 8; q++) acc[q] = 0.f;

    int i = s;
    for (; i + 7 < e; i += 8) {
        int2 ed[8];
        #pragma unroll
        for (int t = 0; t < 8; t++) ed[t] = __ldcs(&d_perm[i + t]);
        uint4 u[8];
        #pragma unroll
        for (int t = 0; t < 8; t++) u[t] = S[(size_t)ed[t].x * 32 + lane];
        #pragma unroll
        for (int t = 0; t < 8; t++) {
            float v = __int_as_float(ed[t].y);
            const __half2* h = (const __half2*)&u[t];
            #pragma unroll
            for (int q = 0; q < 4; q++) {
                float2 f = __half22float2(h[q]);
                acc[q * 2]     += v * f.x;
                acc[q * 2 + 1] += v * f.y;
            }
        }
    }
    for (; i + 3 < e; i += 4) {
        int2 ed[4];
        #pragma unroll
        for (int t = 0; t < 4; t++) ed[t] = __ldcs(&d_perm[i + t]);
        uint4 u[4];
        #pragma unroll
        for (int t = 0; t < 4; t++) u[t] = S[(size_t)ed[t].x * 32 + lane];
        #pragma unroll
        for (int t = 0; t < 4; t++) {
            float v = __int_as_float(ed[t].y);
            const __half2* h = (const __half2*)&u[t];
            #pragma unroll
            for (int q = 0; q < 4; q++) {
                float2 f = __half22float2(h[q]);
                acc[q * 2]     += v * f.x;
                acc[q * 2 + 1] += v * f.y;
            }
        }
    }
    for (; i < e; i++) {
        int2 e0 = __ldcs(&d_perm[i]);
        float v0 = __int_as_float(e0.y);
        uint4 u0 = S[(size_t)e0.x * 32 + lane];
        const __half2* h0 = (const __half2*)&u0;
        #pragma unroll
        for (int q = 0; q < 4; q++) {
            float2 f0 = __half22float2(h0[q]);
            acc[q * 2]     += v0 * f0.x;
            acc[q * 2 + 1] += v0 * f0.y;
        }
    }

    const float4* b4 = (const float4*)bias;
    float4 b0 = b4[lane * 2], b1 = b4[lane * 2 + 1];
    float4 r0, r1;
    r0.x = fmaxf(acc[0] + b0.x, 0.f); r0.y = fmaxf(acc[1] + b0.y, 0.f);
    r0.z = fmaxf(acc[2] + b0.z, 0.f); r0.w = fmaxf(acc[3] + b0.w, 0.f);
    r1.x = fmaxf(acc[4] + b1.x, 0.f); r1.y = fmaxf(acc[5] + b1.y, 0.f);
    r1.z = fmaxf(acc[6] + b1.z, 0.f); r1.w = fmaxf(acc[7] + b1.w, 0.f);

    float4* o = (float4*)out + (size_t)warp * (OUT_DIM / 4) + lane * 2;
    __stcs(o,     r0);
    __stcs(o + 1, r1);
}

// ---------------------------------------------------------------------------
// Launch (R14-validated fork topology, 215.2us).
// ---------------------------------------------------------------------------
extern "C" void kernel_launch(void* const* d_in, const int* in_sizes, int n_in,
                              void* d_out, int out_size) {
    const float* x    = (const float*)d_in[0];   // [100000, 512]
    const float* W    = (const float*)d_in[1];   // [512, 256]
    const float* b    = (const float*)d_in[2];   // [256]
    const int*   erow = (const int*)d_in[3];     // [1600000]
    const int*   ecol = (const int*)d_in[4];     // [1600000]
    const float* eval = (const float*)d_in[5];   // [1600000]
    float* out = (float*)d_out;                  // [100000, 256]

    (void)in_sizes; (void)n_in; (void)out_size;

    // Unconditional (capture-safe, deterministic).
    cudaFuncSetAttribute(gemm_hmma_kernel,
                         cudaFuncAttributeMaxDynamicSharedMemorySize, GEMM_SMEM);

    int prio_lo = 0, prio_hi = 0;
    cudaDeviceGetStreamPriorityRange(&prio_lo, &prio_hi);
    cudaStream_t s2;
    cudaStreamCreateWithPriority(&s2, cudaStreamNonBlocking, prio_hi);
    cudaEvent_t ev_fork, ev_join;
    cudaEventCreateWithFlags(&ev_fork, cudaEventDisableTiming);
    cudaEventCreateWithFlags(&ev_join, cudaEventDisableTiming);

    cudaEventRecord(ev_fork, 0);
    cudaStreamWaitEvent(s2, ev_fork, 0);

    // Main stream: W convert + GEMM (single pass over x).
    convW_kernel<<<(IN_DIM * OUT_DIM + 255) / 256, 256>>>(W);
    gemm_hmma_kernel<<<GEMM_TILES_M, GEMM_THREADS, GEMM_SMEM>>>(x);

    // Side stream (high priority): CSR chain.
    zero_counts_kernel<<<(N_NODES + 255) / 256, 256, 0, s2>>>();
    hist_kernel<<<(N_EDGES / 4 + 255) / 256, 256, 0, s2>>>((const int4*)erow);
    scan_partial_kernel<<<N_SCAN_BLOCKS, SCAN_BLK, 0, s2>>>();
    scan_add_kernel<<<N_SCAN_BLOCKS, SCAN_BLK, 0, s2>>>();
    scatter_kernel<<<(N_EDGES / 8 + 255) / 256, 256, 0, s2>>>(
        (const int4*)erow, (const int4*)ecol, (const float4*)eval);
    cudaEventRecord(ev_join, s2);

    // Join, then SpMM.
    cudaStreamWaitEvent(0, ev_join, 0);
    spmm_kernel<<<(N_NODES * 32 + 255) / 256, 256>>>(b, out);
}